// round 6
// baseline (speedup 1.0000x reference)
#include <cuda_runtime.h>
#include <stdint.h>

// SpikeFP32Floor, round 6: persistent grid-stride kernel, residency-sized
// grid (SMs x 8 blocks x 256 thr = full occupancy, single wave -> no wave
// transitions, no fractional-wave tail). Proven R2/R4 bit logic; 2 quads per
// thread per iteration, next pair prefetched before current stores (MLP=2).
//
// Per 32-quad batch: lane L loads float4 #(base+L); batch covers 512B = 4
// fp32 values. group g=L/8 picks the value, slot s=L%8 picks MSB-first bit
// offsets 4s..4s+3. Nibble -> position 28-4s -> OR-tree over the 8-lane
// group (shfl_xor 1,2,4). floor_bits branchless. Unpack via multiply
// bit-spread, (0-bit) & 0x3F800000 per component. Streaming cache hints.

__device__ __forceinline__ unsigned quad_nib(float4 v) {
    unsigned n;
    n  = (__float_as_uint(v.x) >> 26) & 8u;
    n |= (__float_as_uint(v.y) >> 27) & 4u;
    n |= (__float_as_uint(v.z) >> 28) & 2u;
    n |= (__float_as_uint(v.w) >> 29) & 1u;
    return n;
}

__device__ __forceinline__ unsigned floor_bits(unsigned u) {
    unsigned sgn = u & 0x80000000u;
    unsigned e   = (u >> 23) & 0xFFu;
    int d = 150 - (int)e;
    unsigned shc  = (unsigned)max(0, min(d, 23));
    unsigned mask = (1u << shc) - 1u;
    unsigned t    = u & ~mask;
    bool hasfrac  = (u & mask) != 0u;
    unsigned tm1  = __float_as_uint(__uint_as_float(t) - 1.0f);
    unsigned r    = (sgn && hasfrac) ? tm1 : t;
    if (e < 127u) r = sgn ? 0xBF800000u : 0u;
    return r;
}

__device__ __forceinline__ float4 unpack_nib(unsigned r, unsigned sh) {
    unsigned nib = (r >> sh) & 0xFu;
    unsigned sp  = (nib * 0x00204081u) & 0x01010101u;
    float4 o;
    o.x = __uint_as_float((0u - ((sp >> 24) & 1u)) & 0x3F800000u);
    o.y = __uint_as_float((0u - ((sp >> 16) & 1u)) & 0x3F800000u);
    o.z = __uint_as_float((0u - ((sp >>  8) & 1u)) & 0x3F800000u);
    o.w = __uint_as_float((0u - ( sp        & 1u)) & 0x3F800000u);
    return o;
}

__device__ __forceinline__ unsigned or_tree8(unsigned w) {
    w |= __shfl_xor_sync(0xFFFFFFFFu, w, 1);
    w |= __shfl_xor_sync(0xFFFFFFFFu, w, 2);
    w |= __shfl_xor_sync(0xFFFFFFFFu, w, 4);
    return w;
}

__global__ void __launch_bounds__(256)
spike_floor_v8(const float4* __restrict__ x, float4* __restrict__ out,
               unsigned int nquads)
{
    unsigned lane   = threadIdx.x & 31u;
    unsigned warp   = (blockIdx.x * blockDim.x + threadIdx.x) >> 5;
    unsigned nwarps = (gridDim.x * blockDim.x) >> 5;
    unsigned sh     = 28u - 4u * (lane & 7u);

    size_t stride = (size_t)nwarps * 64u;       // quads per grid-iteration
    size_t q      = (size_t)warp * 64u + lane;  // this warp's first pair
    size_t limit  = (size_t)nquads;

    if (q - lane + 64u > limit) return;

    // Prologue: first pair in flight.
    float4 a = __ldcs(&x[q]);
    float4 b = __ldcs(&x[q + 32u]);

    while (true) {
        unsigned wa = or_tree8(quad_nib(a) << sh);
        unsigned wb = or_tree8(quad_nib(b) << sh);

        float4 oa = unpack_nib(floor_bits(wa), sh);
        float4 ob = unpack_nib(floor_bits(wb), sh);

        size_t qs = q;
        q += stride;
        bool more = (q - lane + 64u <= limit);  // warp-uniform
        if (more) {                              // prefetch next pair
            a = __ldcs(&x[q]);
            b = __ldcs(&x[q + 32u]);
        }

        __stcs(&out[qs],       oa);
        __stcs(&out[qs + 32u], ob);

        if (!more) break;
    }
}

extern "C" void kernel_launch(void* const* d_in, const int* in_sizes, int n_in,
                              void* d_out, int out_size)
{
    const float4* x   = (const float4*)d_in[0];
    float4*       out = (float4*)d_out;

    unsigned n_elems = (unsigned)in_sizes[0];   // 2048*1024*32 floats
    unsigned nquads  = n_elems >> 2;            // float4 count

    int sm_count = 148;
    cudaDeviceGetAttribute(&sm_count, cudaDevAttrMultiProcessorCount, 0);

    const int threads = 256;
    // Full residency: 2048 threads/SM = 8 blocks of 256. Single wave.
    unsigned blocks = (unsigned)sm_count * 8u;

    // Never launch more warps than there are 64-quad batches.
    unsigned max_blocks = (nquads / 64u + 7u) / 8u;
    if (blocks > max_blocks) blocks = max_blocks;
    if (blocks == 0) blocks = 1;

    spike_floor_v8<<<blocks, threads>>>(x, out, nquads);
}

// round 7
// speedup vs baseline: 1.1249x; 1.1249x over previous
#include <cuda_runtime.h>
#include <stdint.h>

// SpikeFP32Floor, round 7 (final form): R2's straight-line structure
// (2 quads/thread, MLP_p1=2, no loop) + R4's cheapest pack/unpack.
//
// Input: 2048*1024 fp32 values, each unpacked MSB-first into 32 floats
// (0.0/1.0). Output: same unpacking of floor(value), bit-exact.
//
// Per 32-quad batch: lane L loads float4 #(base+L); a batch covers 512B =
// 4 fp32 values. group g = L/8 picks the value, slot s = L%8 picks MSB-first
// bit offsets 4s..4s+3. Nibble -> position 28-4s -> OR-tree over the 8-lane
// group (shfl_xor 1,2,4). floor_bits branchless (warp-uniform per group).
// Unpack via multiply bit-spread: (nib * 0x00204081) & 0x01010101 puts nib
// bit k at byte k LSB; component = (0 - bit) & 0x3F800000.
// Streaming cache hints on both sides (zero reuse).

__device__ __forceinline__ unsigned quad_nib(float4 v) {
    // 1.0f = 0x3F800000 (bit 29 set), 0.0f = 0.
    unsigned n;
    n  = (__float_as_uint(v.x) >> 26) & 8u;   // offset 4s   -> nib bit 3
    n |= (__float_as_uint(v.y) >> 27) & 4u;   // offset 4s+1 -> nib bit 2
    n |= (__float_as_uint(v.z) >> 28) & 2u;   // offset 4s+2 -> nib bit 1
    n |= (__float_as_uint(v.w) >> 29) & 1u;   // offset 4s+3 -> nib bit 0
    return n;
}

__device__ __forceinline__ unsigned floor_bits(unsigned u) {
    // e >= 150 -> unchanged; 127<=e<150 -> truncate, minus-1 if negative
    // with fractional bits (exact fp32 sub); e < 127 -> sign?-1.0f:+0.
    unsigned sgn = u & 0x80000000u;
    unsigned e   = (u >> 23) & 0xFFu;
    int d = 150 - (int)e;
    unsigned shc  = (unsigned)max(0, min(d, 23));
    unsigned mask = (1u << shc) - 1u;
    unsigned t    = u & ~mask;
    bool hasfrac  = (u & mask) != 0u;
    unsigned tm1  = __float_as_uint(__uint_as_float(t) - 1.0f);
    unsigned r    = (sgn && hasfrac) ? tm1 : t;
    if (e < 127u) r = sgn ? 0xBF800000u : 0u;
    return r;
}

__device__ __forceinline__ float4 unpack_nib(unsigned r, unsigned sh) {
    unsigned nib = (r >> sh) & 0xFu;
    unsigned sp  = (nib * 0x00204081u) & 0x01010101u;
    float4 o;
    o.x = __uint_as_float((0u - ((sp >> 24) & 1u)) & 0x3F800000u);
    o.y = __uint_as_float((0u - ((sp >> 16) & 1u)) & 0x3F800000u);
    o.z = __uint_as_float((0u - ((sp >>  8) & 1u)) & 0x3F800000u);
    o.w = __uint_as_float((0u - ( sp        & 1u)) & 0x3F800000u);
    return o;
}

__device__ __forceinline__ unsigned or_tree8(unsigned w) {
    w |= __shfl_xor_sync(0xFFFFFFFFu, w, 1);
    w |= __shfl_xor_sync(0xFFFFFFFFu, w, 2);
    w |= __shfl_xor_sync(0xFFFFFFFFu, w, 4);
    return w;
}

__global__ void __launch_bounds__(256)
spike_floor_v9(const float4* __restrict__ x, float4* __restrict__ out,
               unsigned int nquads)
{
    unsigned tid  = blockIdx.x * blockDim.x + threadIdx.x;
    unsigned lane = threadIdx.x & 31u;
    unsigned warp = tid >> 5;

    size_t base = (size_t)warp * 64u;           // 64 quads/warp (2/thread)
    if (base + 64u > (size_t)nquads) return;    // warp-uniform guard

    size_t q0 = base + lane;
    size_t q1 = q0 + 32u;

    // Front-batched pair (MLP_p1 = 2).
    float4 a = __ldcs(&x[q0]);
    float4 b = __ldcs(&x[q1]);

    unsigned sh = 28u - 4u * (lane & 7u);

    unsigned wa = or_tree8(quad_nib(a) << sh);
    unsigned wb = or_tree8(quad_nib(b) << sh);

    float4 oa = unpack_nib(floor_bits(wa), sh);
    float4 ob = unpack_nib(floor_bits(wb), sh);

    __stcs(&out[q0], oa);
    __stcs(&out[q1], ob);
}

extern "C" void kernel_launch(void* const* d_in, const int* in_sizes, int n_in,
                              void* d_out, int out_size)
{
    const float4* x   = (const float4*)d_in[0];
    float4*       out = (float4*)d_out;

    unsigned n_elems = (unsigned)in_sizes[0];   // 2048*1024*32 floats
    unsigned nquads  = n_elems >> 2;            // float4 count
    unsigned threads_total = nquads >> 1;       // 2 quads per thread

    const int threads = 256;
    unsigned blocks = (threads_total + threads - 1) / threads;

    spike_floor_v9<<<blocks, threads>>>(x, out, nquads);
}

// round 8
// speedup vs baseline: 1.1267x; 1.0016x over previous
#include <cuda_runtime.h>
#include <stdint.h>

// SpikeFP32Floor, round 8: identical bit logic and per-thread work to R7
// (the co-best kernel, 82.0us), with the one untried launch knob: 512-thread
// blocks (4 CTAs/SM, same full 2048-thread residency, half the CTA count).
//
// Input: 2048*1024 fp32 values, each unpacked MSB-first into 32 floats
// (0.0/1.0). Output: same unpacking of floor(value), bit-exact.
//
// Per 32-quad batch: lane L loads float4 #(base+L); a batch covers 512B =
// 4 fp32 values. group g = L/8 picks the value, slot s = L%8 picks MSB-first
// bit offsets 4s..4s+3. Nibble -> position 28-4s -> OR-tree over the 8-lane
// group (shfl_xor 1,2,4). floor_bits branchless (warp-uniform per group).
// Unpack via multiply bit-spread. Streaming cache hints (zero reuse).

__device__ __forceinline__ unsigned quad_nib(float4 v) {
    // 1.0f = 0x3F800000 (bit 29 set), 0.0f = 0.
    unsigned n;
    n  = (__float_as_uint(v.x) >> 26) & 8u;   // offset 4s   -> nib bit 3
    n |= (__float_as_uint(v.y) >> 27) & 4u;   // offset 4s+1 -> nib bit 2
    n |= (__float_as_uint(v.z) >> 28) & 2u;   // offset 4s+2 -> nib bit 1
    n |= (__float_as_uint(v.w) >> 29) & 1u;   // offset 4s+3 -> nib bit 0
    return n;
}

__device__ __forceinline__ unsigned floor_bits(unsigned u) {
    // e >= 150 -> unchanged; 127<=e<150 -> truncate, minus-1 if negative
    // with fractional bits (exact fp32 sub); e < 127 -> sign?-1.0f:+0.
    unsigned sgn = u & 0x80000000u;
    unsigned e   = (u >> 23) & 0xFFu;
    int d = 150 - (int)e;
    unsigned shc  = (unsigned)max(0, min(d, 23));
    unsigned mask = (1u << shc) - 1u;
    unsigned t    = u & ~mask;
    bool hasfrac  = (u & mask) != 0u;
    unsigned tm1  = __float_as_uint(__uint_as_float(t) - 1.0f);
    unsigned r    = (sgn && hasfrac) ? tm1 : t;
    if (e < 127u) r = sgn ? 0xBF800000u : 0u;
    return r;
}

__device__ __forceinline__ float4 unpack_nib(unsigned r, unsigned sh) {
    unsigned nib = (r >> sh) & 0xFu;
    unsigned sp  = (nib * 0x00204081u) & 0x01010101u;  // bit k -> byte k LSB
    float4 o;
    o.x = __uint_as_float((0u - ((sp >> 24) & 1u)) & 0x3F800000u);
    o.y = __uint_as_float((0u - ((sp >> 16) & 1u)) & 0x3F800000u);
    o.z = __uint_as_float((0u - ((sp >>  8) & 1u)) & 0x3F800000u);
    o.w = __uint_as_float((0u - ( sp        & 1u)) & 0x3F800000u);
    return o;
}

__device__ __forceinline__ unsigned or_tree8(unsigned w) {
    w |= __shfl_xor_sync(0xFFFFFFFFu, w, 1);
    w |= __shfl_xor_sync(0xFFFFFFFFu, w, 2);
    w |= __shfl_xor_sync(0xFFFFFFFFu, w, 4);
    return w;
}

__global__ void __launch_bounds__(512)
spike_floor_v10(const float4* __restrict__ x, float4* __restrict__ out,
                unsigned int nquads)
{
    unsigned tid  = blockIdx.x * blockDim.x + threadIdx.x;
    unsigned lane = threadIdx.x & 31u;
    unsigned warp = tid >> 5;

    size_t base = (size_t)warp * 64u;           // 64 quads/warp (2/thread)
    if (base + 64u > (size_t)nquads) return;    // warp-uniform guard

    size_t q0 = base + lane;
    size_t q1 = q0 + 32u;

    // Front-batched pair (MLP_p1 = 2).
    float4 a = __ldcs(&x[q0]);
    float4 b = __ldcs(&x[q1]);

    unsigned sh = 28u - 4u * (lane & 7u);

    unsigned wa = or_tree8(quad_nib(a) << sh);
    unsigned wb = or_tree8(quad_nib(b) << sh);

    float4 oa = unpack_nib(floor_bits(wa), sh);
    float4 ob = unpack_nib(floor_bits(wb), sh);

    __stcs(&out[q0], oa);
    __stcs(&out[q1], ob);
}

extern "C" void kernel_launch(void* const* d_in, const int* in_sizes, int n_in,
                              void* d_out, int out_size)
{
    const float4* x   = (const float4*)d_in[0];
    float4*       out = (float4*)d_out;

    unsigned n_elems = (unsigned)in_sizes[0];   // 2048*1024*32 floats
    unsigned nquads  = n_elems >> 2;            // float4 count
    unsigned threads_total = nquads >> 1;       // 2 quads per thread

    const int threads = 512;
    unsigned blocks = (threads_total + threads - 1) / threads;

    spike_floor_v10<<<blocks, threads>>>(x, out, nquads);
}